// round 2
// baseline (speedup 1.0000x reference)
#include <cuda_runtime.h>
#include <math.h>
#include <stdint.h>
#include <stddef.h>

// Problem dims
#define BB    64
#define TT    512
#define EE    768
#define HH    512
#define G3    1536
#define NF    256
#define MALL  (BB*TT)          // 32768

// -------- recurrence persistent-kernel config --------
#define NBLK      128          // co-resident worker CTAs (<= SM count)
#define SH_STRIDE 516          // padded h row stride (bank-conflict free)
#define SMEM_FLOATS (512*48 + 16*SH_STRIDE)
#define SMEM_BYTES  (SMEM_FLOATS*4)

// ----------------- device scratch (statics; no cudaMalloc allowed) ----------
__device__ float g_Gi[(size_t)MALL * G3];      // 201 MB (reused per GRU pass)
__device__ float g_seq0[(size_t)MALL * HH];    // 64 MB: selector hist, later out1
__device__ float g_seq1[(size_t)MALL * HH];    // 64 MB: out0
__device__ float g_newemb[(size_t)MALL * EE];  // 100 MB
__device__ float g_U[(size_t)MALL * (NF*5)];   // 168 MB (conv GEMM out, reused)
__device__ float g_WT[1536 * 768];             // transposed weights scratch
__device__ float g_h[2][BB * HH];              // hidden-state ping-pong
__device__ int   g_sel[BB * TT];
__device__ int   g_order[BB * TT];
__device__ int   g_nsel[BB];
__device__ float g_pooled[BB * 3 * NF];
__device__ unsigned g_bar;

// ---------------------------------------------------------------------------
// reset: zero hidden state + grid-barrier counter (before each recurrence)
// ---------------------------------------------------------------------------
__global__ void k_reset() {
    int i = blockIdx.x * blockDim.x + threadIdx.x;
    if (i == 0) g_bar = 0u;
    if (i < 2 * BB * HH) ((float*)g_h)[i] = 0.f;
}

// ---------------------------------------------------------------------------
// generic transpose: dst[C][R] = src[R][C]   (R, C multiples of 32)
// ---------------------------------------------------------------------------
__global__ void k_transpose(float* dst, const float* src, int R, int C) {
    __shared__ float tile[32][33];
    int c0 = blockIdx.x * 32, r0 = blockIdx.y * 32;
    int tx = threadIdx.x, ty = threadIdx.y;
    #pragma unroll
    for (int i = 0; i < 32; i += 8)
        tile[ty + i][tx] = src[(size_t)(r0 + ty + i) * C + c0 + tx];
    __syncthreads();
    #pragma unroll
    for (int i = 0; i < 32; i += 8)
        dst[(size_t)(c0 + ty + i) * R + r0 + tx] = tile[tx][ty + i];
}

// ---------------------------------------------------------------------------
// GEMM: C[M][N] = A[M][K] @ BT[K][N] (+ bias[n]).  M%128==0, N%128==0, K%16==0
// 128x128 tile, 16-k slab, 256 threads, 8x8 microkernel.
// ---------------------------------------------------------------------------
__global__ __launch_bounds__(256)
void k_gemm(float* __restrict__ C, const float* __restrict__ A,
            const float* __restrict__ BT, const float* __restrict__ bias,
            int M, int N, int K) {
    __shared__ float sA[16][128];
    __shared__ float sB[16][128];
    int tid = threadIdx.x;
    int bm = blockIdx.y * 128;
    int bn = blockIdx.x * 128;
    int tm = (tid >> 4) * 8;     // 0..120
    int tn = (tid & 15) * 8;
    float acc[8][8];
    #pragma unroll
    for (int i = 0; i < 8; i++)
        #pragma unroll
        for (int j = 0; j < 8; j++) acc[i][j] = 0.f;

    for (int k0 = 0; k0 < K; k0 += 16) {
        // load A tile (128 rows x 16 k) as float4, store transposed [k][m]
        #pragma unroll
        for (int i = 0; i < 2; i++) {
            int id = tid * 2 + i;          // 0..511
            int r  = id >> 2;              // 0..127
            int kq = (id & 3) * 4;         // 0,4,8,12
            float4 v = *(const float4*)(A + (size_t)(bm + r) * K + k0 + kq);
            sA[kq + 0][r] = v.x; sA[kq + 1][r] = v.y;
            sA[kq + 2][r] = v.z; sA[kq + 3][r] = v.w;
        }
        // load B tile (16 k x 128 n)
        #pragma unroll
        for (int i = 0; i < 2; i++) {
            int id = tid * 2 + i;
            int kk = id >> 5;              // 0..15
            int nq = (id & 31) * 4;        // 0..124
            *(float4*)&sB[kk][nq] =
                *(const float4*)(BT + (size_t)(k0 + kk) * N + bn + nq);
        }
        __syncthreads();
        #pragma unroll
        for (int k = 0; k < 16; k++) {
            float a[8], b[8];
            *(float4*)(a)     = *(const float4*)&sA[k][tm];
            *(float4*)(a + 4) = *(const float4*)&sA[k][tm + 4];
            *(float4*)(b)     = *(const float4*)&sB[k][tn];
            *(float4*)(b + 4) = *(const float4*)&sB[k][tn + 4];
            #pragma unroll
            for (int i = 0; i < 8; i++)
                #pragma unroll
                for (int j = 0; j < 8; j++)
                    acc[i][j] += a[i] * b[j];
        }
        __syncthreads();
    }
    #pragma unroll
    for (int i = 0; i < 8; i++) {
        size_t row = (size_t)(bm + tm + i) * N + bn + tn;
        #pragma unroll
        for (int j = 0; j < 8; j += 4) {
            float4 v;
            v.x = acc[i][j + 0]; v.y = acc[i][j + 1];
            v.z = acc[i][j + 2]; v.w = acc[i][j + 3];
            if (bias) {
                v.x += bias[bn + tn + j + 0]; v.y += bias[bn + tn + j + 1];
                v.z += bias[bn + tn + j + 2]; v.w += bias[bn + tn + j + 3];
            }
            *(float4*)(C + row + j) = v;
        }
    }
}

// ---------------------------------------------------------------------------
// persistent GRU recurrence. grid = 128 blocks (4 b-tiles x 32 j-tiles), 256 thr.
// Whh slice (48 rows x 512) pinned in smem; h ping-pongs in global (L2).
// hist[(b*T+t)*H + j] = masked output; Gi[(b*T+t)*1536 + {j,512+j,1024+j}].
// ---------------------------------------------------------------------------
__global__ __launch_bounds__(256, 1)
void k_recur(const float* __restrict__ Gi, float* __restrict__ hist,
             const float* __restrict__ Whh, const float* __restrict__ bhh,
             const int* __restrict__ nsel) {
    extern __shared__ float sm[];
    float* sW = sm;                 // [k][48]: 3 gates x 16 j
    float* sh = sm + 512 * 48;      // [16 b][SH_STRIDE]
    int tid = threadIdx.x;
    int bt = blockIdx.x & 3, jt = blockIdx.x >> 2;
    int b0 = bt * 16, j0 = jt * 16;
    int jj = tid & 15, bb = tid >> 4;
    int b = b0 + bb, j = j0 + jj;

    // load Whh slice: local rows r = g*16 + jl -> global row g*512 + j0 + jl
    for (int idx = tid; idx < 48 * 512; idx += 256) {
        int r = idx >> 9;           // 0..47
        int k = idx & 511;
        int g = r >> 4, jl = r & 15;
        sW[k * 48 + r] = Whh[(size_t)(g * 512 + j0 + jl) * 512 + k];
    }
    float br = bhh[j], bz = bhh[512 + j], bn2 = bhh[1024 + j];
    int lim = nsel ? nsel[b] : TT;
    __syncthreads();

    unsigned bar_target = 0;
    for (int t = 0; t < TT; t++) {
        const float* hsrc = g_h[t & 1];
        // stage h tile (16 b x 512) into smem
        #pragma unroll
        for (int i = 0; i < 8; i++) {
            int id = tid + i * 256;        // 0..2047 float4 slots
            int lb = id >> 7;              // 0..15
            int lk = (id & 127) * 4;
            float4 v = *(const float4*)(hsrc + (size_t)(b0 + lb) * HH + lk);
            *(float4*)&sh[lb * SH_STRIDE + lk] = v;
        }
        __syncthreads();

        const float* shb = sh + bb * SH_STRIDE;
        float ar = br, az = bz, an = bn2;
        #pragma unroll 8
        for (int k = 0; k < 512; k++) {
            float hv = shb[k];
            ar += hv * sW[k * 48 + jj];
            az += hv * sW[k * 48 + 16 + jj];
            an += hv * sW[k * 48 + 32 + jj];
        }
        size_t grow = ((size_t)b * TT + t) * (size_t)G3;
        float gir = Gi[grow + j];
        float giz = Gi[grow + 512 + j];
        float gin = Gi[grow + 1024 + j];
        float r = 1.f / (1.f + expf(-(gir + ar)));
        float z = 1.f / (1.f + expf(-(giz + az)));
        float n = tanhf(gin + r * an);
        float hold = shb[j];
        float hn = (1.f - z) * n + z * hold;
        bool valid = t < lim;
        float hnew = valid ? hn : hold;
        float y    = valid ? hn : 0.f;
        hist[((size_t)b * TT + t) * HH + j] = y;
        g_h[(t + 1) & 1][b * HH + j] = hnew;

        // grid barrier (monotonic counter)
        __syncthreads();
        if (tid == 0) {
            __threadfence();
            atomicAdd(&g_bar, 1u);
            bar_target += NBLK;
            while (*(volatile unsigned*)&g_bar < bar_target) { }
            __threadfence();
        }
        __syncthreads();
    }
}

// ---------------------------------------------------------------------------
// selector logits + argmax: one warp per (b,t) over stored hidden history
// ---------------------------------------------------------------------------
__global__ void k_selargmax(const float* __restrict__ hist,
                            const float* __restrict__ Ws,
                            const float* __restrict__ bs) {
    int gw = (blockIdx.x * blockDim.x + threadIdx.x) >> 5;
    int lane = threadIdx.x & 31;
    if (gw >= BB * TT) return;
    const float* h = hist + (size_t)gw * HH;
    float l0 = 0.f, l1 = 0.f;
    #pragma unroll 4
    for (int jv = lane; jv < HH; jv += 32) {
        float hv = h[jv];
        l0 += hv * Ws[jv];
        l1 += hv * Ws[HH + jv];
    }
    #pragma unroll
    for (int o = 16; o; o >>= 1) {
        l0 += __shfl_down_sync(0xffffffffu, l0, o);
        l1 += __shfl_down_sync(0xffffffffu, l1, o);
    }
    if (lane == 0)
        g_sel[gw] = ((l1 + bs[1]) > (l0 + bs[0])) ? 1 : 0;
}

// ---------------------------------------------------------------------------
// lens from mask, sel fixes, stable partition -> order + nsel (1 warp / batch)
// ---------------------------------------------------------------------------
__global__ void k_fix(const int* __restrict__ mask) {
    int b = blockIdx.x;
    int lane = threadIdx.x;
    int len = 0;
    for (int t = lane; t < TT; t += 32) len += mask[b * TT + t];
    #pragma unroll
    for (int o = 16; o; o >>= 1) len += __shfl_down_sync(0xffffffffu, len, o);
    len = __shfl_sync(0xffffffffu, len, 0);
    int cnt = 0;
    for (int c = 0; c < TT; c += 32) {
        int t = c + lane;
        int s = g_sel[b * TT + t];
        if (t == 0) s = 1;
        if (t == len - 1) s = 1;
        if (t >= len) s = 0;
        unsigned bal = __ballot_sync(0xffffffffu, s);
        int pre = __popc(bal & ((1u << lane) - 1u));
        if (s) g_order[b * TT + cnt + pre] = t;
        cnt += __popc(bal);
    }
    if (lane == 0) g_nsel[b] = cnt;
}

// ---------------------------------------------------------------------------
// gather: new_emb[b][p][:] = emb[b][order[p]][:] for p < nsel else 0
// ---------------------------------------------------------------------------
__global__ void k_gather(const float* __restrict__ emb, float* __restrict__ dst) {
    int row = blockIdx.x;               // b*T + p
    int b = row >> 9, p = row & 511;
    float4 v = make_float4(0.f, 0.f, 0.f, 0.f);
    if (p < g_nsel[b]) {
        int t = g_order[row];
        v = ((const float4*)(emb + ((size_t)b * TT + t) * EE))[threadIdx.x];
    }
    ((float4*)(dst + (size_t)row * EE))[threadIdx.x] = v;
}

// ---------------------------------------------------------------------------
// conv pool: pooled[b][seg+f] = max_t relu(bc[f] + sum_dt U[b][t+dt][f*kw+dt])
// ---------------------------------------------------------------------------
__global__ void k_pool(const float* __restrict__ U, const float* __restrict__ bc,
                       int kw, int Nn, int seg) {
    int b = blockIdx.x;
    int f = threadIdx.x;                 // 256 = NF
    float bcv = bc[f];
    float m = 0.f;
    const float* Ub = U + (size_t)b * TT * Nn + (size_t)f * kw;
    for (int t = 0; t <= TT - kw; t++) {
        float s = bcv;
        for (int dt = 0; dt < kw; dt++)
            s += Ub[(size_t)(t + dt) * Nn + dt];
        m = fmaxf(m, fmaxf(s, 0.f));
    }
    g_pooled[b * (3 * NF) + seg + f] = m;
}

// ---------------------------------------------------------------------------
// final: out[b] = pooled[b] . Wo + bo
// ---------------------------------------------------------------------------
__global__ void k_final(const float* __restrict__ Wo, const float* __restrict__ bo,
                        float* __restrict__ out) {
    __shared__ float red[256];
    int b = blockIdx.x, tid = threadIdx.x;
    float s = 0.f;
    for (int f = tid; f < 3 * NF; f += 256)
        s += g_pooled[b * (3 * NF) + f] * Wo[f];
    red[tid] = s;
    __syncthreads();
    for (int o = 128; o; o >>= 1) {
        if (tid < o) red[tid] += red[tid + o];
        __syncthreads();
    }
    if (tid == 0) out[b] = red[0] + bo[0];
}

// ---------------------------------------------------------------------------
extern "C" void kernel_launch(void* const* d_in, const int* in_sizes, int n_in,
                              void* d_out, int out_size) {
    const float* emb   = (const float*)d_in[0];
    const int*   mask  = (const int*)  d_in[1];
    const float* Wih_c = (const float*)d_in[2];
    const float* Whh_c = (const float*)d_in[3];
    const float* bih_c = (const float*)d_in[4];
    const float* bhh_c = (const float*)d_in[5];
    const float* Ws    = (const float*)d_in[6];
    const float* bs    = (const float*)d_in[7];
    const float* Wih0  = (const float*)d_in[8];
    const float* Whh0  = (const float*)d_in[9];
    const float* bih0  = (const float*)d_in[10];
    const float* bhh0  = (const float*)d_in[11];
    const float* Wih1  = (const float*)d_in[12];
    const float* Whh1  = (const float*)d_in[13];
    const float* bih1  = (const float*)d_in[14];
    const float* bhh1  = (const float*)d_in[15];
    const float* Wc3   = (const float*)d_in[16];
    const float* bc3   = (const float*)d_in[17];
    const float* Wc4   = (const float*)d_in[18];
    const float* bc4   = (const float*)d_in[19];
    const float* Wc5   = (const float*)d_in[20];
    const float* bc5   = (const float*)d_in[21];
    const float* Wo    = (const float*)d_in[22];
    const float* bo    = (const float*)d_in[23];
    float* out = (float*)d_out;

    cudaFuncSetAttribute(k_recur, cudaFuncAttributeMaxDynamicSharedMemorySize,
                         SMEM_BYTES);

    float *pGi, *pS0, *pS1, *pNe, *pU, *pWT;
    int* pNsel;
    cudaGetSymbolAddress((void**)&pGi,   g_Gi);
    cudaGetSymbolAddress((void**)&pS0,   g_seq0);
    cudaGetSymbolAddress((void**)&pS1,   g_seq1);
    cudaGetSymbolAddress((void**)&pNe,   g_newemb);
    cudaGetSymbolAddress((void**)&pU,    g_U);
    cudaGetSymbolAddress((void**)&pWT,   g_WT);
    cudaGetSymbolAddress((void**)&pNsel, g_nsel);

    dim3 t32x8(32, 8);

    // ---- selector GRU ----
    k_transpose<<<dim3(EE/32, G3/32), t32x8>>>(pWT, Wih_c, G3, EE);
    k_gemm<<<dim3(G3/128, MALL/128), 256>>>(pGi, emb, pWT, bih_c, MALL, G3, EE);
    k_reset<<<256, 256>>>();
    k_recur<<<NBLK, 256, SMEM_BYTES>>>(pGi, pS0, Whh_c, bhh_c, nullptr);
    k_selargmax<<<(BB*TT*32 + 255)/256, 256>>>(pS0, Ws, bs);
    k_fix<<<BB, 32>>>(mask);
    k_gather<<<MALL, EE/4>>>(emb, pNe);

    // ---- layer 0 ----
    k_transpose<<<dim3(EE/32, G3/32), t32x8>>>(pWT, Wih0, G3, EE);
    k_gemm<<<dim3(G3/128, MALL/128), 256>>>(pGi, pNe, pWT, bih0, MALL, G3, EE);
    k_reset<<<256, 256>>>();
    k_recur<<<NBLK, 256, SMEM_BYTES>>>(pGi, pS1, Whh0, bhh0, pNsel);

    // ---- layer 1 ----
    k_transpose<<<dim3(HH/32, G3/32), t32x8>>>(pWT, Wih1, G3, HH);
    k_gemm<<<dim3(G3/128, MALL/128), 256>>>(pGi, pS1, pWT, bih1, MALL, G3, HH);
    k_reset<<<256, 256>>>();
    k_recur<<<NBLK, 256, SMEM_BYTES>>>(pGi, pS0, Whh1, bhh1, pNsel);

    // ---- convs (GEMM + pool), kw = 3,4,5 ----
    k_transpose<<<dim3(HH/32, (NF*3)/32), t32x8>>>(pWT, Wc3, NF*3, HH);
    k_gemm<<<dim3((NF*3)/128, MALL/128), 256>>>(pU, pS0, pWT, nullptr, MALL, NF*3, HH);
    k_pool<<<BB, NF>>>(pU, bc3, 3, NF*3, 0);

    k_transpose<<<dim3(HH/32, (NF*4)/32), t32x8>>>(pWT, Wc4, NF*4, HH);
    k_gemm<<<dim3((NF*4)/128, MALL/128), 256>>>(pU, pS0, pWT, nullptr, MALL, NF*4, HH);
    k_pool<<<BB, NF>>>(pU, bc4, 4, NF*4, NF);

    k_transpose<<<dim3(HH/32, (NF*5)/32), t32x8>>>(pWT, Wc5, NF*5, HH);
    k_gemm<<<dim3((NF*5)/128, MALL/128), 256>>>(pU, pS0, pWT, nullptr, MALL, NF*5, HH);
    k_pool<<<BB, NF>>>(pU, bc5, 5, NF*5, 2*NF);

    // ---- final projection ----
    k_final<<<BB, 256>>>(Wo, bo, out);
}

// round 3
// speedup vs baseline: 1.3460x; 1.3460x over previous
#include <cuda_runtime.h>
#include <math.h>
#include <stdint.h>
#include <stddef.h>

typedef unsigned long long u64;

// Problem dims
#define BB    64
#define TT    512
#define EE    768
#define HH    512
#define G3    1536
#define NF    256
#define MALL  (BB*TT)          // 32768

// -------- recurrence persistent-kernel config --------
#define NBLK      128          // co-resident worker CTAs (<= SM count)
#define SHS       512          // h row stride in smem
#define RSM_FLOATS (16*SHS + 16*8*3*16)   // sh + red
#define RSM_BYTES  (RSM_FLOATS*4)         // 57344 B

// ----------------- device scratch (statics; no cudaMalloc allowed) ----------
__device__ float g_Gi[(size_t)MALL * G3];      // 201 MB (reused per GRU pass)
__device__ float g_seq0[(size_t)MALL * HH];    // selector hist, later out1
__device__ float g_seq1[(size_t)MALL * HH];    // out0
__device__ float g_newemb[(size_t)MALL * EE];
__device__ float g_U[(size_t)MALL * (NF*5)];   // conv GEMM out (reused)
__device__ float g_WT[G3 * EE];                // transposed weights scratch
__device__ float g_h[2][BB * HH];              // hidden-state ping-pong
__device__ int   g_sel[BB * TT];
__device__ int   g_order[BB * TT];
__device__ int   g_nsel[BB];
__device__ float g_pooled[BB * 3 * NF];
__device__ unsigned g_bar;

// ----------------------------- f32x2 helpers --------------------------------
__device__ __forceinline__ void fma2(u64& d, u64 a, u64 b) {
    asm("fma.rn.f32x2 %0,%1,%2,%0;" : "+l"(d) : "l"(a), "l"(b));
}
__device__ __forceinline__ u64 add2(u64 a, u64 b) {
    u64 r; asm("add.rn.f32x2 %0,%1,%2;" : "=l"(r) : "l"(a), "l"(b)); return r;
}
__device__ __forceinline__ float2 unpk(u64 v) {
    float2 r; asm("mov.b64 {%0,%1},%2;" : "=f"(r.x), "=f"(r.y) : "l"(v)); return r;
}
__device__ __forceinline__ u64 shx16(u64 v) {
    unsigned lo = (unsigned)v, hi = (unsigned)(v >> 32);
    lo = __shfl_xor_sync(0xffffffffu, lo, 16);
    hi = __shfl_xor_sync(0xffffffffu, hi, 16);
    return ((u64)hi << 32) | (u64)lo;
}

// ---------------------------------------------------------------------------
// reset: zero hidden state + grid-barrier counter (before each recurrence)
// ---------------------------------------------------------------------------
__global__ void k_reset() {
    int i = blockIdx.x * blockDim.x + threadIdx.x;
    if (i == 0) g_bar = 0u;
    if (i < 2 * BB * HH) ((float*)g_h)[i] = 0.f;
}
__global__ void k_zero_pooled() {
    int i = blockIdx.x * blockDim.x + threadIdx.x;
    if (i < BB * 3 * NF) g_pooled[i] = 0.f;
}

// ---------------------------------------------------------------------------
// generic transpose: dst[C][R] = src[R][C]   (R, C multiples of 32)
// ---------------------------------------------------------------------------
__global__ void k_transpose(float* dst, const float* src, int R, int C) {
    __shared__ float tile[32][33];
    int c0 = blockIdx.x * 32, r0 = blockIdx.y * 32;
    int tx = threadIdx.x, ty = threadIdx.y;
    #pragma unroll
    for (int i = 0; i < 32; i += 8)
        tile[ty + i][tx] = src[(size_t)(r0 + ty + i) * C + c0 + tx];
    __syncthreads();
    #pragma unroll
    for (int i = 0; i < 32; i += 8)
        dst[(size_t)(c0 + ty + i) * R + r0 + tx] = tile[tx][ty + i];
}

// ---------------------------------------------------------------------------
// GEMM (f32x2 packed): C[M][N] = A[M][K] @ BT[K][N] (+ bias[n]).
// 128x128 tile, 16-k slab, 256 threads. Per thread: 8 m-rows (4 f32x2 pairs)
// x 8 n-cols (strided by 16). B stored DUPLICATED in smem so the broadcast
// operand is a single conflict-free LDS.64.
// ---------------------------------------------------------------------------
__global__ __launch_bounds__(256)
void k_gemm(float* __restrict__ C, const float* __restrict__ A,
            const float* __restrict__ BT, const float* __restrict__ bias,
            int M, int N, int K) {
    __shared__ float sA[16][128];
    __shared__ float sBd[16][256];   // duplicated: [k][2n] = [k][2n+1] = B[k][n]
    int tid = threadIdx.x;
    int bm = blockIdx.y * 128;
    int bn = blockIdx.x * 128;
    int tmRow = (tid >> 4) * 8;      // 8 m-rows, contiguous
    int tn = tid & 15;               // n-cols: tn + 16*s, s=0..7

    u64 acc[4][8];
    #pragma unroll
    for (int i = 0; i < 4; i++)
        #pragma unroll
        for (int s = 0; s < 8; s++) acc[i][s] = 0ull;

    for (int k0 = 0; k0 < K; k0 += 16) {
        // A tile: 128 rows x 16 k -> sA[k][m]
        #pragma unroll
        for (int i = 0; i < 2; i++) {
            int id = tid * 2 + i;          // 0..511
            int r  = id >> 2;              // 0..127
            int kq = (id & 3) * 4;
            float4 v = *(const float4*)(A + (size_t)(bm + r) * K + k0 + kq);
            sA[kq + 0][r] = v.x; sA[kq + 1][r] = v.y;
            sA[kq + 2][r] = v.z; sA[kq + 3][r] = v.w;
        }
        // B tile duplicated: sBd[k][2n..2n+1] = (v,v)
        #pragma unroll
        for (int i = 0; i < 2; i++) {
            int id = tid * 2 + i;
            int kk = id >> 5;              // 0..15
            int nq = (id & 31) * 4;        // 0..124
            float4 v = *(const float4*)(BT + (size_t)(k0 + kk) * N + bn + nq);
            *(float4*)&sBd[kk][2*nq]     = make_float4(v.x, v.x, v.y, v.y);
            *(float4*)&sBd[kk][2*nq + 4] = make_float4(v.z, v.z, v.w, v.w);
        }
        __syncthreads();
        #pragma unroll
        for (int k = 0; k < 16; k++) {
            ulonglong2 a01 = *(const ulonglong2*)&sA[k][tmRow];      // (m0,m1),(m2,m3)
            ulonglong2 a23 = *(const ulonglong2*)&sA[k][tmRow + 4];  // (m4,m5),(m6,m7)
            #pragma unroll
            for (int s = 0; s < 8; s++) {
                u64 bv = *(const u64*)&sBd[k][2 * (tn + 16 * s)];
                fma2(acc[0][s], a01.x, bv);
                fma2(acc[1][s], a01.y, bv);
                fma2(acc[2][s], a23.x, bv);
                fma2(acc[3][s], a23.y, bv);
            }
        }
        __syncthreads();
    }
    // epilogue
    #pragma unroll
    for (int ip = 0; ip < 4; ip++) {
        size_t r0 = (size_t)(bm + tmRow + 2 * ip) * N;
        size_t r1 = r0 + N;
        #pragma unroll
        for (int s = 0; s < 8; s++) {
            int col = bn + tn + 16 * s;
            float2 v = unpk(acc[ip][s]);
            float bv = bias ? bias[col] : 0.f;
            C[r0 + col] = v.x + bv;
            C[r1 + col] = v.y + bv;
        }
    }
}

// ---------------------------------------------------------------------------
// persistent GRU recurrence, register-resident weights + k-packed f32x2.
// grid = 128 CTAs (4 b-tiles x 32 j-tiles), 256 threads.
// Phase1: thread (jj = tid&15, kc = tid>>4) holds w[3][32k] in regs (as 48
//         f32x2 pairs), loops 16 b, partial dot over its 32-k chunk.
//         Warp shfl-xor(16) pairs the two kc chunks; smem 'red' collects the
//         8-warp partials. Bank conflicts avoided by XOR-4 read-order on the
//         odd kc chunk, mirrored in weight-register order.
// Phase2: thread (bb = tid>>4, jj = tid&15) sums 8 partials/gate + bias,
//         applies gate math, writes hist + g_h ping-pong. Grid barrier.
// ---------------------------------------------------------------------------
__global__ __launch_bounds__(256, 1)
void k_recur(const float* __restrict__ Gi, float* __restrict__ hist,
             const float* __restrict__ Whh, const float* __restrict__ bhh,
             const int* __restrict__ nsel) {
    extern __shared__ float sm[];
    float* sh  = sm;               // [16 b][SHS]
    float* red = sm + 16 * SHS;    // [16 b][8 warp][3 gate][16 jj]
    int tid = threadIdx.x;
    int bt = blockIdx.x & 3, jt = blockIdx.x >> 2;
    int b0 = bt * 16, j0 = jt * 16;

    // phase1 mapping
    int jj = tid & 15;
    int kc = tid >> 4;             // 16 chunks of 32 k
    int k0 = kc * 32;
    int qx = (kc & 1) << 2;        // bank-conflict-avoiding read permutation
    int wi = tid >> 5;
    int lane = tid & 31;
    // phase2 mapping
    int bb2 = tid >> 4;
    int j2 = j0 + jj;
    int b2 = b0 + bb2;

    // weights -> registers, ordered to match the permuted h-read sequence
    u64 w2[3][16];
    #pragma unroll
    for (int g = 0; g < 3; g++) {
        const float* wrow = Whh + (size_t)(g * 512 + j0 + jj) * 512;
        #pragma unroll
        for (int q = 0; q < 8; q++) {
            int keff = k0 + 4 * (q ^ qx);
            w2[g][2*q + 0] = *(const u64*)(wrow + keff);
            w2[g][2*q + 1] = *(const u64*)(wrow + keff + 2);
        }
    }
    float br = bhh[j2], bz = bhh[512 + j2], bn2 = bhh[1024 + j2];
    int lim = nsel ? nsel[b2] : TT;
    unsigned bar_t = 0;

    for (int t = 0; t < TT; t++) {
        const float* hsrc = g_h[t & 1];
        // stage h tile (16 b x 512) into smem, bypassing L1
        #pragma unroll
        for (int i = 0; i < 8; i++) {
            int id = tid + i * 256;
            int lb = id >> 7;
            int lk = (id & 127) * 4;
            float4 v = __ldcg((const float4*)(hsrc + (size_t)(b0 + lb) * HH + lk));
            *(float4*)&sh[lb * SHS + lk] = v;
        }
        __syncthreads();

        // phase1: partial dots over this thread's 32-k chunk, all 16 b
        #pragma unroll 1
        for (int b = 0; b < 16; b++) {
            const ulonglong2* hp = (const ulonglong2*)&sh[b * SHS + k0];
            u64 a0 = 0ull, a1 = 0ull, a2 = 0ull;
            #pragma unroll
            for (int q = 0; q < 8; q++) {
                ulonglong2 hv = hp[q ^ qx];
                fma2(a0, hv.x, w2[0][2*q]); fma2(a0, hv.y, w2[0][2*q + 1]);
                fma2(a1, hv.x, w2[1][2*q]); fma2(a1, hv.y, w2[1][2*q + 1]);
                fma2(a2, hv.x, w2[2][2*q]); fma2(a2, hv.y, w2[2][2*q + 1]);
            }
            a0 = add2(a0, shx16(a0));
            a1 = add2(a1, shx16(a1));
            a2 = add2(a2, shx16(a2));
            if (lane < 16) {
                float2 f0 = unpk(a0), f1 = unpk(a1), f2 = unpk(a2);
                int base = b * 384 + wi * 48 + jj;
                red[base]      = f0.x + f0.y;
                red[base + 16] = f1.x + f1.y;
                red[base + 32] = f2.x + f2.y;
            }
        }
        __syncthreads();

        // phase2: gates for (b2, j2)
        float sr = br, sz = bz, sn = bn2;
        #pragma unroll
        for (int w = 0; w < 8; w++) {
            int base = bb2 * 384 + w * 48 + jj;
            sr += red[base];
            sz += red[base + 16];
            sn += red[base + 32];
        }
        const float* gp = Gi + ((size_t)b2 * TT + t) * G3;
        float gir = __ldcg(gp + j2);
        float giz = __ldcg(gp + 512 + j2);
        float gin = __ldcg(gp + 1024 + j2);
        float r = 1.f / (1.f + expf(-(gir + sr)));
        float z = 1.f / (1.f + expf(-(giz + sz)));
        float n = tanhf(gin + r * sn);
        float hold = sh[bb2 * SHS + j2];
        float hn = (1.f - z) * n + z * hold;
        bool valid = t < lim;
        hist[((size_t)b2 * TT + t) * HH + j2] = valid ? hn : 0.f;
        g_h[(t + 1) & 1][b2 * HH + j2] = valid ? hn : hold;

        // grid barrier (monotonic counter)
        __threadfence();
        __syncthreads();
        if (tid == 0) {
            atomicAdd(&g_bar, 1u);
            bar_t += NBLK;
            while (*(volatile unsigned*)&g_bar < bar_t) { }
            __threadfence();
        }
        __syncthreads();
    }
}

// ---------------------------------------------------------------------------
// selector logits + argmax: one warp per (b,t) over stored hidden history
// ---------------------------------------------------------------------------
__global__ void k_selargmax(const float* __restrict__ hist,
                            const float* __restrict__ Ws,
                            const float* __restrict__ bs) {
    int gw = (blockIdx.x * blockDim.x + threadIdx.x) >> 5;
    int lane = threadIdx.x & 31;
    if (gw >= BB * TT) return;
    const float* h = hist + (size_t)gw * HH;
    float l0 = 0.f, l1 = 0.f;
    #pragma unroll 4
    for (int jv = lane; jv < HH; jv += 32) {
        float hv = h[jv];
        l0 += hv * Ws[jv];
        l1 += hv * Ws[HH + jv];
    }
    #pragma unroll
    for (int o = 16; o; o >>= 1) {
        l0 += __shfl_down_sync(0xffffffffu, l0, o);
        l1 += __shfl_down_sync(0xffffffffu, l1, o);
    }
    if (lane == 0)
        g_sel[gw] = ((l1 + bs[1]) > (l0 + bs[0])) ? 1 : 0;
}

// ---------------------------------------------------------------------------
// lens from mask, sel fixes, stable partition -> order + nsel (1 warp / batch)
// ---------------------------------------------------------------------------
__global__ void k_fix(const int* __restrict__ mask) {
    int b = blockIdx.x;
    int lane = threadIdx.x;
    int len = 0;
    for (int t = lane; t < TT; t += 32) len += mask[b * TT + t];
    #pragma unroll
    for (int o = 16; o; o >>= 1) len += __shfl_down_sync(0xffffffffu, len, o);
    len = __shfl_sync(0xffffffffu, len, 0);
    int cnt = 0;
    for (int c = 0; c < TT; c += 32) {
        int t = c + lane;
        int s = g_sel[b * TT + t];
        if (t == 0) s = 1;
        if (t == len - 1) s = 1;
        if (t >= len) s = 0;
        unsigned bal = __ballot_sync(0xffffffffu, s);
        int pre = __popc(bal & ((1u << lane) - 1u));
        if (s) g_order[b * TT + cnt + pre] = t;
        cnt += __popc(bal);
    }
    if (lane == 0) g_nsel[b] = cnt;
}

// ---------------------------------------------------------------------------
// gather: new_emb[b][p][:] = emb[b][order[p]][:] for p < nsel else 0
// ---------------------------------------------------------------------------
__global__ void k_gather(const float* __restrict__ emb, float* __restrict__ dst) {
    int row = blockIdx.x;               // b*T + p
    int b = row >> 9, p = row & 511;
    float4 v = make_float4(0.f, 0.f, 0.f, 0.f);
    if (p < g_nsel[b]) {
        int t = g_order[row];
        v = ((const float4*)(emb + ((size_t)b * TT + t) * EE))[threadIdx.x];
    }
    ((float4*)(dst + (size_t)row * EE))[threadIdx.x] = v;
}

// ---------------------------------------------------------------------------
// conv pool (t-split x8, atomicMax; all values >= 0 so int-compare is valid)
// ---------------------------------------------------------------------------
__global__ void k_pool(const float* __restrict__ U, const float* __restrict__ bc,
                       int kw, int Nn, int seg) {
    int b = blockIdx.x;
    int f = threadIdx.x;                 // 256 = NF
    int tlim = TT - kw + 1;
    int t0 = blockIdx.y * 64;
    int t1 = t0 + 64 < tlim ? t0 + 64 : tlim;
    float bcv = bc[f];
    float m = 0.f;
    const float* Ub = U + (size_t)b * TT * Nn + (size_t)f * kw;
    for (int t = t0; t < t1; t++) {
        float s = bcv;
        #pragma unroll 5
        for (int dt = 0; dt < kw; dt++)
            s += Ub[(size_t)(t + dt) * Nn + dt];
        m = fmaxf(m, fmaxf(s, 0.f));
    }
    atomicMax((int*)&g_pooled[b * (3 * NF) + seg + f], __float_as_int(m));
}

// ---------------------------------------------------------------------------
// final: out[b] = pooled[b] . Wo + bo
// ---------------------------------------------------------------------------
__global__ void k_final(const float* __restrict__ Wo, const float* __restrict__ bo,
                        float* __restrict__ out) {
    __shared__ float redf[256];
    int b = blockIdx.x, tid = threadIdx.x;
    float s = 0.f;
    for (int f = tid; f < 3 * NF; f += 256)
        s += g_pooled[b * (3 * NF) + f] * Wo[f];
    redf[tid] = s;
    __syncthreads();
    for (int o = 128; o; o >>= 1) {
        if (tid < o) redf[tid] += redf[tid + o];
        __syncthreads();
    }
    if (tid == 0) out[b] = redf[0] + bo[0];
}

// ---------------------------------------------------------------------------
extern "C" void kernel_launch(void* const* d_in, const int* in_sizes, int n_in,
                              void* d_out, int out_size) {
    const float* emb   = (const float*)d_in[0];
    const int*   mask  = (const int*)  d_in[1];
    const float* Wih_c = (const float*)d_in[2];
    const float* Whh_c = (const float*)d_in[3];
    const float* bih_c = (const float*)d_in[4];
    const float* bhh_c = (const float*)d_in[5];
    const float* Ws    = (const float*)d_in[6];
    const float* bs    = (const float*)d_in[7];
    const float* Wih0  = (const float*)d_in[8];
    const float* Whh0  = (const float*)d_in[9];
    const float* bih0  = (const float*)d_in[10];
    const float* bhh0  = (const float*)d_in[11];
    const float* Wih1  = (const float*)d_in[12];
    const float* Whh1  = (const float*)d_in[13];
    const float* bih1  = (const float*)d_in[14];
    const float* bhh1  = (const float*)d_in[15];
    const float* Wc3   = (const float*)d_in[16];
    const float* bc3   = (const float*)d_in[17];
    const float* Wc4   = (const float*)d_in[18];
    const float* bc4   = (const float*)d_in[19];
    const float* Wc5   = (const float*)d_in[20];
    const float* bc5   = (const float*)d_in[21];
    const float* Wo    = (const float*)d_in[22];
    const float* bo    = (const float*)d_in[23];
    float* out = (float*)d_out;

    cudaFuncSetAttribute(k_recur, cudaFuncAttributeMaxDynamicSharedMemorySize,
                         RSM_BYTES);

    float *pGi, *pS0, *pS1, *pNe, *pU, *pWT;
    int* pNsel;
    cudaGetSymbolAddress((void**)&pGi,   g_Gi);
    cudaGetSymbolAddress((void**)&pS0,   g_seq0);
    cudaGetSymbolAddress((void**)&pS1,   g_seq1);
    cudaGetSymbolAddress((void**)&pNe,   g_newemb);
    cudaGetSymbolAddress((void**)&pU,    g_U);
    cudaGetSymbolAddress((void**)&pWT,   g_WT);
    cudaGetSymbolAddress((void**)&pNsel, g_nsel);

    dim3 t32x8(32, 8);

    // ---- selector GRU ----
    k_transpose<<<dim3(EE/32, G3/32), t32x8>>>(pWT, Wih_c, G3, EE);
    k_gemm<<<dim3(G3/128, MALL/128), 256>>>(pGi, emb, pWT, bih_c, MALL, G3, EE);
    k_reset<<<256, 256>>>();
    k_recur<<<NBLK, 256, RSM_BYTES>>>(pGi, pS0, Whh_c, bhh_c, nullptr);
    k_selargmax<<<(BB*TT*32 + 255)/256, 256>>>(pS0, Ws, bs);
    k_fix<<<BB, 32>>>(mask);
    k_gather<<<MALL, EE/4>>>(emb, pNe);

    // ---- layer 0 ----
    k_transpose<<<dim3(EE/32, G3/32), t32x8>>>(pWT, Wih0, G3, EE);
    k_gemm<<<dim3(G3/128, MALL/128), 256>>>(pGi, pNe, pWT, bih0, MALL, G3, EE);
    k_reset<<<256, 256>>>();
    k_recur<<<NBLK, 256, RSM_BYTES>>>(pGi, pS1, Whh0, bhh0, pNsel);

    // ---- layer 1 ----
    k_transpose<<<dim3(HH/32, G3/32), t32x8>>>(pWT, Wih1, G3, HH);
    k_gemm<<<dim3(G3/128, MALL/128), 256>>>(pGi, pS1, pWT, bih1, MALL, G3, HH);
    k_reset<<<256, 256>>>();
    k_recur<<<NBLK, 256, RSM_BYTES>>>(pGi, pS0, Whh1, bhh1, pNsel);

    // ---- convs (GEMM + pool), kw = 3,4,5 ----
    k_zero_pooled<<<(BB*3*NF + 255)/256, 256>>>();

    k_transpose<<<dim3(HH/32, (NF*3)/32), t32x8>>>(pWT, Wc3, NF*3, HH);
    k_gemm<<<dim3((NF*3)/128, MALL/128), 256>>>(pU, pS0, pWT, nullptr, MALL, NF*3, HH);
    k_pool<<<dim3(BB, 8), NF>>>(pU, bc3, 3, NF*3, 0);

    k_transpose<<<dim3(HH/32, (NF*4)/32), t32x8>>>(pWT, Wc4, NF*4, HH);
    k_gemm<<<dim3((NF*4)/128, MALL/128), 256>>>(pU, pS0, pWT, nullptr, MALL, NF*4, HH);
    k_pool<<<dim3(BB, 8), NF>>>(pU, bc4, 4, NF*4, NF);

    k_transpose<<<dim3(HH/32, (NF*5)/32), t32x8>>>(pWT, Wc5, NF*5, HH);
    k_gemm<<<dim3((NF*5)/128, MALL/128), 256>>>(pU, pS0, pWT, nullptr, MALL, NF*5, HH);
    k_pool<<<dim3(BB, 8), NF>>>(pU, bc5, 5, NF*5, 2*NF);

    // ---- final projection ----
    k_final<<<BB, 256>>>(Wo, bo, out);
}

// round 4
// speedup vs baseline: 1.4956x; 1.1112x over previous
#include <cuda_runtime.h>
#include <math.h>
#include <stdint.h>
#include <stddef.h>

typedef unsigned long long u64;

// Problem dims
#define BB    64
#define TT    512
#define EE    768
#define HH    512
#define G3    1536
#define NF    256
#define MALL  (BB*TT)          // 32768

// -------- recurrence persistent-kernel config --------
#define NBLK      128          // co-resident worker CTAs
#define SHS       512          // h row stride in smem
#define REDS      392          // red stride (mod 32 != 0 -> conflict-free)
#define RSM_FLOATS (16*SHS + 16*REDS)
#define RSM_BYTES  (RSM_FLOATS*4)

// ----------------- device scratch (statics; no cudaMalloc allowed) ----------
__device__ float g_Gi[(size_t)MALL * G3];      // reused per GRU pass
__device__ float g_seq0[(size_t)MALL * HH];    // selector hist, later out1
__device__ float g_seq1[(size_t)MALL * HH];    // out0
__device__ float g_newemb[(size_t)MALL * EE];
__device__ float g_U[(size_t)MALL * (NF*5)];   // conv GEMM out (reused)
__device__ float g_WT[G3 * EE];                // transposed weights scratch
__device__ float g_h[2][BB * HH];              // hidden-state ping-pong
__device__ int   g_sel[BB * TT];
__device__ int   g_order[BB * TT];
__device__ int   g_nsel[BB];
__device__ float g_pooled[BB * 3 * NF];
__device__ unsigned g_bar4[4 * 32];            // per-b-tile barrier counters

// ----------------------------- f32x2 helpers --------------------------------
__device__ __forceinline__ void fma2(u64& d, u64 a, u64 b) {
    asm("fma.rn.f32x2 %0,%1,%2,%0;" : "+l"(d) : "l"(a), "l"(b));
}
__device__ __forceinline__ u64 add2(u64 a, u64 b) {
    u64 r; asm("add.rn.f32x2 %0,%1,%2;" : "=l"(r) : "l"(a), "l"(b)); return r;
}
__device__ __forceinline__ float2 unpk(u64 v) {
    float2 r; asm("mov.b64 {%0,%1},%2;" : "=f"(r.x), "=f"(r.y) : "l"(v)); return r;
}
__device__ __forceinline__ u64 dup2(unsigned v) {
    u64 r; asm("mov.b64 %0,{%1,%1};" : "=l"(r) : "r"(v)); return r;
}
__device__ __forceinline__ u64 shx16(u64 v) {
    unsigned lo = (unsigned)v, hi = (unsigned)(v >> 32);
    lo = __shfl_xor_sync(0xffffffffu, lo, 16);
    hi = __shfl_xor_sync(0xffffffffu, hi, 16);
    return ((u64)hi << 32) | (u64)lo;
}

// ---------------------------------------------------------------------------
__global__ void k_reset() {
    int i = blockIdx.x * blockDim.x + threadIdx.x;
    if (i < 4 * 32) g_bar4[i] = 0u;
    if (i < 2 * BB * HH) ((float*)g_h)[i] = 0.f;
}
__global__ void k_zero_pooled() {
    int i = blockIdx.x * blockDim.x + threadIdx.x;
    if (i < BB * 3 * NF) g_pooled[i] = 0.f;
}

// ---------------------------------------------------------------------------
// generic transpose: dst[C][R] = src[R][C]   (R, C multiples of 32)
// ---------------------------------------------------------------------------
__global__ void k_transpose(float* dst, const float* src, int R, int C) {
    __shared__ float tile[32][33];
    int c0 = blockIdx.x * 32, r0 = blockIdx.y * 32;
    int tx = threadIdx.x, ty = threadIdx.y;
    #pragma unroll
    for (int i = 0; i < 32; i += 8)
        tile[ty + i][tx] = src[(size_t)(r0 + ty + i) * C + c0 + tx];
    __syncthreads();
    #pragma unroll
    for (int i = 0; i < 32; i += 8)
        dst[(size_t)(c0 + ty + i) * R + r0 + tx] = tile[tx][ty + i];
}

// ---------------------------------------------------------------------------
// GEMM (f32x2, FFMA2-bound): C[M][N] = A[M][K] @ BT[K][N] (+ bias[n]).
// 256x128 tile, 16-k slab, 256 threads, double-buffered smem.
// Per thread: 16 m-rows (8 f32x2 pairs) x 8 n-cols (stride 16).
// B loaded as LDS.32 and duplicated into both lanes in registers.
// ---------------------------------------------------------------------------
__global__ __launch_bounds__(256, 1)
void k_gemm(float* __restrict__ C, const float* __restrict__ A,
            const float* __restrict__ BT, const float* __restrict__ bias,
            int M, int N, int K) {
    __shared__ float sA[2][16][256];   // 32 KB
    __shared__ float sB[2][16][128];   // 16 KB
    int tid = threadIdx.x;
    int bm = blockIdx.y * 256;
    int bn = blockIdx.x * 128;
    int tm = (tid >> 4) * 16;          // 16 m-rows
    int tn = tid & 15;                 // n: tn + 16*s

    float4 ra[4]; float4 rb[2];

    u64 acc[8][8];
    #pragma unroll
    for (int i = 0; i < 8; i++)
        #pragma unroll
        for (int s = 0; s < 8; s++) acc[i][s] = 0ull;

    // load slab 0
    #pragma unroll
    for (int i = 0; i < 4; i++) {
        int id = i * 256 + tid, r = id >> 2, kq = (id & 3) * 4;
        ra[i] = *(const float4*)(A + (size_t)(bm + r) * K + kq);
    }
    #pragma unroll
    for (int i = 0; i < 2; i++) {
        int id = i * 256 + tid, kk = id >> 5, nq = (id & 31) * 4;
        rb[i] = *(const float4*)(BT + (size_t)kk * N + bn + nq);
    }
    #pragma unroll
    for (int i = 0; i < 4; i++) {
        int id = i * 256 + tid, r = id >> 2, kq = (id & 3) * 4;
        sA[0][kq + 0][r] = ra[i].x; sA[0][kq + 1][r] = ra[i].y;
        sA[0][kq + 2][r] = ra[i].z; sA[0][kq + 3][r] = ra[i].w;
    }
    #pragma unroll
    for (int i = 0; i < 2; i++) {
        int id = i * 256 + tid, kk = id >> 5, nq = (id & 31) * 4;
        *(float4*)&sB[0][kk][nq] = rb[i];
    }
    __syncthreads();

    int nslab = K >> 4;
    for (int s = 0; s < nslab; s++) {
        int buf = s & 1;
        if (s + 1 < nslab) {
            int k0 = (s + 1) * 16;
            #pragma unroll
            for (int i = 0; i < 4; i++) {
                int id = i * 256 + tid, r = id >> 2, kq = (id & 3) * 4;
                ra[i] = *(const float4*)(A + (size_t)(bm + r) * K + k0 + kq);
            }
            #pragma unroll
            for (int i = 0; i < 2; i++) {
                int id = i * 256 + tid, kk = id >> 5, nq = (id & 31) * 4;
                rb[i] = *(const float4*)(BT + (size_t)(k0 + kk) * N + bn + nq);
            }
        }
        #pragma unroll
        for (int k = 0; k < 16; k++) {
            u64 a[8];
            *(ulonglong2*)&a[0] = *(const ulonglong2*)&sA[buf][k][tm];
            *(ulonglong2*)&a[2] = *(const ulonglong2*)&sA[buf][k][tm + 4];
            *(ulonglong2*)&a[4] = *(const ulonglong2*)&sA[buf][k][tm + 8];
            *(ulonglong2*)&a[6] = *(const ulonglong2*)&sA[buf][k][tm + 12];
            #pragma unroll
            for (int sn = 0; sn < 8; sn++) {
                unsigned bv = *(const unsigned*)&sB[buf][k][tn + 16 * sn];
                u64 b2 = dup2(bv);
                #pragma unroll
                for (int i = 0; i < 8; i++)
                    fma2(acc[i][sn], a[i], b2);
            }
        }
        if (s + 1 < nslab) {
            int nb = buf ^ 1;
            #pragma unroll
            for (int i = 0; i < 4; i++) {
                int id = i * 256 + tid, r = id >> 2, kq = (id & 3) * 4;
                sA[nb][kq + 0][r] = ra[i].x; sA[nb][kq + 1][r] = ra[i].y;
                sA[nb][kq + 2][r] = ra[i].z; sA[nb][kq + 3][r] = ra[i].w;
            }
            #pragma unroll
            for (int i = 0; i < 2; i++) {
                int id = i * 256 + tid, kk = id >> 5, nq = (id & 31) * 4;
                *(float4*)&sB[nb][kk][nq] = rb[i];
            }
            __syncthreads();
        }
    }
    // epilogue
    #pragma unroll
    for (int i = 0; i < 8; i++) {
        size_t r0 = (size_t)(bm + tm + 2 * i) * N;
        size_t r1 = r0 + N;
        #pragma unroll
        for (int sn = 0; sn < 8; sn++) {
            int col = bn + tn + 16 * sn;
            float2 v = unpk(acc[i][sn]);
            float bv = bias ? bias[col] : 0.f;
            C[r0 + col] = v.x + bv;
            C[r1 + col] = v.y + bv;
        }
    }
}

// ---------------------------------------------------------------------------
// persistent GRU recurrence, register-resident weights + k-packed f32x2.
// grid = 128 CTAs (4 b-tiles x 32 j-tiles), 256 threads.
// Per-b-tile barriers (32 arrivals each); Gi prefetched at loop top.
// ---------------------------------------------------------------------------
__global__ __launch_bounds__(256, 1)
void k_recur(const float* __restrict__ Gi, float* __restrict__ hist,
             const float* __restrict__ Whh, const float* __restrict__ bhh,
             const int* __restrict__ nsel) {
    extern __shared__ float sm[];
    float* sh  = sm;               // [16 b][SHS]
    float* red = sm + 16 * SHS;    // [16 b][REDS]: 8 warp x 3 gate x 16 jj
    int tid = threadIdx.x;
    int bt = blockIdx.x & 3, jt = blockIdx.x >> 2;
    int b0 = bt * 16, j0 = jt * 16;

    int jj = tid & 15;
    int kc = tid >> 4;             // 16 chunks of 32 k
    int k0 = kc * 32;
    int qx = (kc & 1) << 2;        // bank-conflict-avoiding permutation
    int wi = tid >> 5;
    int lane = tid & 31;
    int bb2 = tid >> 4;
    int j2 = j0 + jj;
    int b2 = b0 + bb2;

    // weights -> registers, ordered to match permuted h-read sequence
    u64 w2[3][16];
    #pragma unroll
    for (int g = 0; g < 3; g++) {
        const float* wrow = Whh + (size_t)(g * 512 + j0 + jj) * 512;
        #pragma unroll
        for (int q = 0; q < 8; q++) {
            int keff = k0 + 4 * (q ^ qx);
            w2[g][2*q + 0] = *(const u64*)(wrow + keff);
            w2[g][2*q + 1] = *(const u64*)(wrow + keff + 2);
        }
    }
    float br = bhh[j2], bz = bhh[512 + j2], bn2 = bhh[1024 + j2];
    int lim = nsel ? nsel[b2] : TT;
    unsigned bar_t = 0;
    unsigned* barp = &g_bar4[bt * 32];

    for (int t = 0; t < TT; t++) {
        // prefetch Gi (independent of h)
        const float* gp = Gi + ((size_t)b2 * TT + t) * G3;
        float gir = __ldcg(gp + j2);
        float giz = __ldcg(gp + 512 + j2);
        float gin = __ldcg(gp + 1024 + j2);

        const float* hsrc = g_h[t & 1];
        #pragma unroll
        for (int i = 0; i < 8; i++) {
            int id = tid + i * 256;
            int lb = id >> 7;
            int lk = (id & 127) * 4;
            float4 v = __ldcg((const float4*)(hsrc + (size_t)(b0 + lb) * HH + lk));
            *(float4*)&sh[lb * SHS + lk] = v;
        }
        __syncthreads();

        // phase1: partial dots over this thread's 32-k chunk, all 16 b
        #pragma unroll 1
        for (int b = 0; b < 16; b++) {
            const ulonglong2* hp = (const ulonglong2*)&sh[b * SHS + k0];
            u64 a0 = 0ull, a1 = 0ull, a2 = 0ull;
            #pragma unroll
            for (int q = 0; q < 8; q++) {
                ulonglong2 hv = hp[q ^ qx];
                fma2(a0, hv.x, w2[0][2*q]); fma2(a0, hv.y, w2[0][2*q + 1]);
                fma2(a1, hv.x, w2[1][2*q]); fma2(a1, hv.y, w2[1][2*q + 1]);
                fma2(a2, hv.x, w2[2][2*q]); fma2(a2, hv.y, w2[2][2*q + 1]);
            }
            a0 = add2(a0, shx16(a0));
            a1 = add2(a1, shx16(a1));
            a2 = add2(a2, shx16(a2));
            if (lane < 16) {
                float2 f0 = unpk(a0), f1 = unpk(a1), f2 = unpk(a2);
                int base = b * REDS + wi * 48 + jj;
                red[base]      = f0.x + f0.y;
                red[base + 16] = f1.x + f1.y;
                red[base + 32] = f2.x + f2.y;
            }
        }
        __syncthreads();

        // phase2: gates for (b2, j2)
        float sr = br, sz = bz, sn = bn2;
        #pragma unroll
        for (int w = 0; w < 8; w++) {
            int base = bb2 * REDS + w * 48 + jj;
            sr += red[base];
            sz += red[base + 16];
            sn += red[base + 32];
        }
        float r = 1.f / (1.f + expf(-(gir + sr)));
        float z = 1.f / (1.f + expf(-(giz + sz)));
        float n = tanhf(gin + r * sn);
        float hold = sh[bb2 * SHS + j2];
        float hn = (1.f - z) * n + z * hold;
        bool valid = t < lim;
        g_h[(t + 1) & 1][b2 * HH + j2] = valid ? hn : hold;
        hist[((size_t)b2 * TT + t) * HH + j2] = valid ? hn : 0.f;

        // per-b-tile barrier (32 arrivals)
        __threadfence();
        __syncthreads();
        if (tid == 0) {
            atomicAdd(barp, 1u);
            bar_t += 32;
            while (*(volatile unsigned*)barp < bar_t) { }
            __threadfence();
        }
        __syncthreads();
    }
}

// ---------------------------------------------------------------------------
__global__ void k_selargmax(const float* __restrict__ hist,
                            const float* __restrict__ Ws,
                            const float* __restrict__ bs) {
    int gw = (blockIdx.x * blockDim.x + threadIdx.x) >> 5;
    int lane = threadIdx.x & 31;
    if (gw >= BB * TT) return;
    const float* h = hist + (size_t)gw * HH;
    float l0 = 0.f, l1 = 0.f;
    #pragma unroll 4
    for (int jv = lane; jv < HH; jv += 32) {
        float hv = h[jv];
        l0 += hv * Ws[jv];
        l1 += hv * Ws[HH + jv];
    }
    #pragma unroll
    for (int o = 16; o; o >>= 1) {
        l0 += __shfl_down_sync(0xffffffffu, l0, o);
        l1 += __shfl_down_sync(0xffffffffu, l1, o);
    }
    if (lane == 0)
        g_sel[gw] = ((l1 + bs[1]) > (l0 + bs[0])) ? 1 : 0;
}

// ---------------------------------------------------------------------------
__global__ void k_fix(const int* __restrict__ mask) {
    int b = blockIdx.x;
    int lane = threadIdx.x;
    int len = 0;
    for (int t = lane; t < TT; t += 32) len += mask[b * TT + t];
    #pragma unroll
    for (int o = 16; o; o >>= 1) len += __shfl_down_sync(0xffffffffu, len, o);
    len = __shfl_sync(0xffffffffu, len, 0);
    int cnt = 0;
    for (int c = 0; c < TT; c += 32) {
        int t = c + lane;
        int s = g_sel[b * TT + t];
        if (t == 0) s = 1;
        if (t == len - 1) s = 1;
        if (t >= len) s = 0;
        unsigned bal = __ballot_sync(0xffffffffu, s);
        int pre = __popc(bal & ((1u << lane) - 1u));
        if (s) g_order[b * TT + cnt + pre] = t;
        cnt += __popc(bal);
    }
    if (lane == 0) g_nsel[b] = cnt;
}

// ---------------------------------------------------------------------------
__global__ void k_gather(const float* __restrict__ emb, float* __restrict__ dst) {
    int row = blockIdx.x;               // b*T + p
    int b = row >> 9, p = row & 511;
    float4 v = make_float4(0.f, 0.f, 0.f, 0.f);
    if (p < g_nsel[b]) {
        int t = g_order[row];
        v = ((const float4*)(emb + ((size_t)b * TT + t) * EE))[threadIdx.x];
    }
    ((float4*)(dst + (size_t)row * EE))[threadIdx.x] = v;
}

// ---------------------------------------------------------------------------
__global__ void k_pool(const float* __restrict__ U, const float* __restrict__ bc,
                       int kw, int Nn, int seg) {
    int b = blockIdx.x;
    int f = threadIdx.x;
    int tlim = TT - kw + 1;
    int t0 = blockIdx.y * 64;
    int t1 = t0 + 64 < tlim ? t0 + 64 : tlim;
    float bcv = bc[f];
    float m = 0.f;
    const float* Ub = U + (size_t)b * TT * Nn + (size_t)f * kw;
    for (int t = t0; t < t1; t++) {
        float s = bcv;
        #pragma unroll 5
        for (int dt = 0; dt < kw; dt++)
            s += Ub[(size_t)(t + dt) * Nn + dt];
        m = fmaxf(m, fmaxf(s, 0.f));
    }
    atomicMax((int*)&g_pooled[b * (3 * NF) + seg + f], __float_as_int(m));
}

// ---------------------------------------------------------------------------
__global__ void k_final(const float* __restrict__ Wo, const float* __restrict__ bo,
                        float* __restrict__ out) {
    __shared__ float redf[256];
    int b = blockIdx.x, tid = threadIdx.x;
    float s = 0.f;
    for (int f = tid; f < 3 * NF; f += 256)
        s += g_pooled[b * (3 * NF) + f] * Wo[f];
    redf[tid] = s;
    __syncthreads();
    for (int o = 128; o; o >>= 1) {
        if (tid < o) redf[tid] += redf[tid + o];
        __syncthreads();
    }
    if (tid == 0) out[b] = redf[0] + bo[0];
}

// ---------------------------------------------------------------------------
extern "C" void kernel_launch(void* const* d_in, const int* in_sizes, int n_in,
                              void* d_out, int out_size) {
    const float* emb   = (const float*)d_in[0];
    const int*   mask  = (const int*)  d_in[1];
    const float* Wih_c = (const float*)d_in[2];
    const float* Whh_c = (const float*)d_in[3];
    const float* bih_c = (const float*)d_in[4];
    const float* bhh_c = (const float*)d_in[5];
    const float* Ws    = (const float*)d_in[6];
    const float* bs    = (const float*)d_in[7];
    const float* Wih0  = (const float*)d_in[8];
    const float* Whh0  = (const float*)d_in[9];
    const float* bih0  = (const float*)d_in[10];
    const float* bhh0  = (const float*)d_in[11];
    const float* Wih1  = (const float*)d_in[12];
    const float* Whh1  = (const float*)d_in[13];
    const float* bih1  = (const float*)d_in[14];
    const float* bhh1  = (const float*)d_in[15];
    const float* Wc3   = (const float*)d_in[16];
    const float* bc3   = (const float*)d_in[17];
    const float* Wc4   = (const float*)d_in[18];
    const float* bc4   = (const float*)d_in[19];
    const float* Wc5   = (const float*)d_in[20];
    const float* bc5   = (const float*)d_in[21];
    const float* Wo    = (const float*)d_in[22];
    const float* bo    = (const float*)d_in[23];
    float* out = (float*)d_out;

    cudaFuncSetAttribute(k_recur, cudaFuncAttributeMaxDynamicSharedMemorySize,
                         RSM_BYTES);

    float *pGi, *pS0, *pS1, *pNe, *pU, *pWT;
    int* pNsel;
    cudaGetSymbolAddress((void**)&pGi,   g_Gi);
    cudaGetSymbolAddress((void**)&pS0,   g_seq0);
    cudaGetSymbolAddress((void**)&pS1,   g_seq1);
    cudaGetSymbolAddress((void**)&pNe,   g_newemb);
    cudaGetSymbolAddress((void**)&pU,    g_U);
    cudaGetSymbolAddress((void**)&pWT,   g_WT);
    cudaGetSymbolAddress((void**)&pNsel, g_nsel);

    dim3 t32x8(32, 8);

    // ---- selector GRU ----
    k_transpose<<<dim3(EE/32, G3/32), t32x8>>>(pWT, Wih_c, G3, EE);
    k_gemm<<<dim3(G3/128, MALL/256), 256>>>(pGi, emb, pWT, bih_c, MALL, G3, EE);
    k_reset<<<256, 256>>>();
    k_recur<<<NBLK, 256, RSM_BYTES>>>(pGi, pS0, Whh_c, bhh_c, nullptr);
    k_selargmax<<<(BB*TT*32 + 255)/256, 256>>>(pS0, Ws, bs);
    k_fix<<<BB, 32>>>(mask);
    k_gather<<<MALL, EE/4>>>(emb, pNe);

    // ---- layer 0 ----
    k_transpose<<<dim3(EE/32, G3/32), t32x8>>>(pWT, Wih0, G3, EE);
    k_gemm<<<dim3(G3/128, MALL/256), 256>>>(pGi, pNe, pWT, bih0, MALL, G3, EE);
    k_reset<<<256, 256>>>();
    k_recur<<<NBLK, 256, RSM_BYTES>>>(pGi, pS1, Whh0, bhh0, pNsel);

    // ---- layer 1 ----
    k_transpose<<<dim3(HH/32, G3/32), t32x8>>>(pWT, Wih1, G3, HH);
    k_gemm<<<dim3(G3/128, MALL/256), 256>>>(pGi, pS1, pWT, bih1, MALL, G3, HH);
    k_reset<<<256, 256>>>();
    k_recur<<<NBLK, 256, RSM_BYTES>>>(pGi, pS0, Whh1, bhh1, pNsel);

    // ---- convs (GEMM + pool), kw = 3,4,5 ----
    k_zero_pooled<<<(BB*3*NF + 255)/256, 256>>>();

    k_transpose<<<dim3(HH/32, (NF*3)/32), t32x8>>>(pWT, Wc3, NF*3, HH);
    k_gemm<<<dim3((NF*3)/128, MALL/256), 256>>>(pU, pS0, pWT, nullptr, MALL, NF*3, HH);
    k_pool<<<dim3(BB, 8), NF>>>(pU, bc3, 3, NF*3, 0);

    k_transpose<<<dim3(HH/32, (NF*4)/32), t32x8>>>(pWT, Wc4, NF*4, HH);
    k_gemm<<<dim3((NF*4)/128, MALL/256), 256>>>(pU, pS0, pWT, nullptr, MALL, NF*4, HH);
    k_pool<<<dim3(BB, 8), NF>>>(pU, bc4, 4, NF*4, NF);

    k_transpose<<<dim3(HH/32, (NF*5)/32), t32x8>>>(pWT, Wc5, NF*5, HH);
    k_gemm<<<dim3((NF*5)/128, MALL/256), 256>>>(pU, pS0, pWT, nullptr, MALL, NF*5, HH);
    k_pool<<<dim3(BB, 8), NF>>>(pU, bc5, 5, NF*5, 2*NF);

    // ---- final projection ----
    k_final<<<BB, 256>>>(Wo, bo, out);
}